// round 17
// baseline (speedup 1.0000x reference)
#include <cuda_runtime.h>
#include <cuda_fp16.h>
#include <math.h>

// ---------------------------------------------------------------------------
// Problem constants
// ---------------------------------------------------------------------------
#define BB    128
#define TT    384
#define HH    1024
#define N3    3072
#define KK    1024
#define KP    (KK/2)        // 512 fp16-pairs per row
#define MFULL (BB*TT)

#define NBLK  128           // persistent recurrence blocks (1/SM)
#define NCH   16            // h chunks per step (64 elems each)
#define RTH   384           // recurrence threads (12 warps)

#define WPAIRS  (N3*KP)     // 1,572,864 pairs per weight matrix
#define INPAIRS (MFULL*KP)  // 25,165,824 pairs
#define HPAIRS  (BB*KP)     // 65,536 pairs

// ---------------------------------------------------------------------------
// Scratch (device globals -- allocation-free per harness rules)
// ---------------------------------------------------------------------------
__device__ float g_xg [(size_t)MFULL * N3];        // fp32 input projections
__device__ uint2 g_inS [(size_t)MFULL * KP];       // split rand_input
__device__ uint2 g_yAS [(size_t)MFULL * KP];       // split layer out ping
__device__ uint2 g_yBS [(size_t)MFULL * KP];       // split layer out pong
__device__ uint2 g_WihS[2][(size_t)N3 * KP];       // split Wih (L0, L1)
__device__ uint2 g_WhhS[2][(size_t)N3 * KP];       // split Whh (L0, L1)
__device__ uint2 g_hA  [BB * KP];                  // h0 layer0 / pass3 init
__device__ uint2 g_hB  [BB * KP];                  // h0 layer1 / pass4 init
__device__ uint2 g_hC  [BB * KP];                  // ping-pong scratch

// ---------------------------------------------------------------------------
// Tree grid barrier (validated R14/R15): 16-wide groups -> 8-wide root,
// monotonic counters, nanosleep backoff.
// ---------------------------------------------------------------------------
__device__ unsigned g_grp[8 * 64];     // 256 B stride between group counters
__device__ unsigned g_root = 0;
__device__ volatile unsigned g_gen = 0;

__device__ __forceinline__ void grid_sync(unsigned /*nb*/)
{
    __syncthreads();
    if (threadIdx.x == 0) {
        unsigned old = g_gen;
        __threadfence();                               // release prior writes
        unsigned o = atomicAdd(&g_grp[(blockIdx.x >> 4) * 64], 1u);
        if ((o & 15u) == 15u) {                        // last in group
            unsigned r = atomicAdd(&g_root, 1u);
            if ((r & 7u) == 7u)                        // last group
                atomicAdd((unsigned*)&g_gen, 1u);      // open gate
        }
        while (g_gen == old) __nanosleep(64);
        __threadfence();                               // acquire
    }
    __syncthreads();
}

// ---------------------------------------------------------------------------
// Helpers: fp16 hi/lo split pairs, cp.async, m16n8k16 mma
// ---------------------------------------------------------------------------
__device__ __forceinline__ uint2 splitpair(float x0, float x1)
{
    __half h0 = __float2half_rn(x0), h1 = __float2half_rn(x1);
    float  r0 = x0 - __half2float(h0), r1 = x1 - __half2float(h1);
    __half l0 = __float2half_rn(r0), l1 = __float2half_rn(r1);
    uint2 u;
    u.x = (unsigned)__half_as_ushort(h0) | ((unsigned)__half_as_ushort(h1) << 16);
    u.y = (unsigned)__half_as_ushort(l0) | ((unsigned)__half_as_ushort(l1) << 16);
    return u;
}
__device__ __forceinline__ float lo_f(unsigned u) { return __half2float(__ushort_as_half((unsigned short)(u & 0xFFFF))); }
__device__ __forceinline__ float hi_f(unsigned u) { return __half2float(__ushort_as_half((unsigned short)(u >> 16))); }

__device__ __forceinline__ unsigned sptr(const void* p)
{ return (unsigned)__cvta_generic_to_shared(p); }
__device__ __forceinline__ void cpa16(unsigned d, const void* s)
{ asm volatile("cp.async.cg.shared.global [%0], [%1], 16;" :: "r"(d), "l"(s)); }
#define CP_COMMIT() asm volatile("cp.async.commit_group;")
#define CP_WAIT1()  asm volatile("cp.async.wait_group 1;")
#define CP_WAIT0()  asm volatile("cp.async.wait_group 0;")

__device__ __forceinline__ void mma_f16(float* d, unsigned a0, unsigned a1,
                                        unsigned a2, unsigned a3,
                                        unsigned b0, unsigned b1)
{
    asm volatile(
        "mma.sync.aligned.m16n8k16.row.col.f32.f16.f16.f32 "
        "{%0,%1,%2,%3}, {%4,%5,%6,%7}, {%8,%9}, {%0,%1,%2,%3};"
        : "+f"(d[0]), "+f"(d[1]), "+f"(d[2]), "+f"(d[3])
        : "r"(a0), "r"(a1), "r"(a2), "r"(a3), "r"(b0), "r"(b1));
}
// 3xFP16: d += Ahi*Blo + Alo*Bhi + Ahi*Bhi
__device__ __forceinline__ void mma3h(float* d, uint2 A0, uint2 A1, uint2 A2,
                                      uint2 A3, uint2 B0, uint2 B1)
{
    mma_f16(d, A0.x, A1.x, A2.x, A3.x, B0.y, B1.y);
    mma_f16(d, A0.y, A1.y, A2.y, A3.y, B0.x, B1.x);
    mma_f16(d, A0.x, A1.x, A2.x, A3.x, B0.x, B1.x);
}

// ---------------------------------------------------------------------------
// Prep kernel 1: split rand_input + both h0 layers (one launch)
// ---------------------------------------------------------------------------
__global__ __launch_bounds__(256) void prep_misc(
    const float2* __restrict__ rin, const float2* __restrict__ h0,
    uint2* __restrict__ inS, uint2* __restrict__ hA, uint2* __restrict__ hB)
{
    int i = blockIdx.x * 256 + threadIdx.x;
    if (i < INPAIRS) {
        float2 v = rin[i]; inS[i] = splitpair(v.x, v.y); return;
    }
    i -= INPAIRS;
    if (i < HPAIRS) {
        float2 v = h0[i]; hA[i] = splitpair(v.x, v.y); return;
    }
    i -= HPAIRS;
    if (i < HPAIRS) {
        float2 v = h0[HPAIRS + i]; hB[i] = splitpair(v.x, v.y);
    }
}

// ---------------------------------------------------------------------------
// Prep kernel 2: split all 4 weight matrices (one launch)
// ---------------------------------------------------------------------------
__global__ __launch_bounds__(256) void prep_weights(
    const float2* __restrict__ w0, const float2* __restrict__ w1,
    const float2* __restrict__ w2, const float2* __restrict__ w3,
    uint2* __restrict__ d0, uint2* __restrict__ d1,
    uint2* __restrict__ d2, uint2* __restrict__ d3)
{
    int i = blockIdx.x * 256 + threadIdx.x;
    if (i >= 4 * WPAIRS) return;
    int m = i / WPAIRS, r = i - m * WPAIRS;
    const float2* s = (m == 0) ? w0 : (m == 1) ? w1 : (m == 2) ? w2 : w3;
    uint2*        d = (m == 0) ? d0 : (m == 1) ? d1 : (m == 2) ? d2 : d3;
    float2 v = s[r];
    d[r] = splitpair(v.x, v.y);
}

// ---------------------------------------------------------------------------
// xg GEMM (fp16-3x): unchanged (measured component of the 41.5 ms run).
// ---------------------------------------------------------------------------
#define XG_SMEM ((2*(128*16) + 2*(64*16)) * (int)sizeof(uint2))   // 49152 B

__global__ __launch_bounds__(256) void gemm_xg(
    const uint2* __restrict__ A, const uint2* __restrict__ W,
    const float* __restrict__ bias, float* __restrict__ C)
{
    extern __shared__ uint2 smv[];
    uint2* sA[2] = { smv,            smv + 128*16 };
    uint2* sB[2] = { smv + 2*128*16, smv + 2*128*16 + 64*16 };

    const int tid  = threadIdx.x;
    const int lane = tid & 31;
    const int w    = tid >> 5;
    const int wm   = w & 3, wn = w >> 2;
    const int qr   = lane >> 2;
    const int lq   = lane & 3;
    const int m0   = blockIdx.y * 128;
    const int n0   = blockIdx.x * 64;

    float D[2][4][4] = {};

    auto stage = [&](int kc, int s) {
        #pragma unroll
        for (int u = 0; u < 4; ++u) {
            int gi = tid + u * 256;
            int row = gi >> 3, g = gi & 7;
            const uint2* src = A + (size_t)(m0 + row) * KP + kc * 16 + g * 2;
            int ks = (g * 2) ^ ((row & 3) << 2);
            cpa16(sptr(sA[s] + row * 16 + ks), src);
        }
        #pragma unroll
        for (int u = 0; u < 2; ++u) {
            int gi = tid + u * 256;
            int row = gi >> 3, g = gi & 7;
            const uint2* src = W + (size_t)(n0 + row) * KP + kc * 16 + g * 2;
            int ks = (g * 2) ^ ((row & 3) << 2);
            cpa16(sptr(sB[s] + row * 16 + ks), src);
        }
        CP_COMMIT();
    };

    stage(0, 0);
    for (int kc = 0; kc < 32; ++kc) {
        if (kc < 31) { stage(kc + 1, (kc + 1) & 1); CP_WAIT1(); }
        else         { CP_WAIT0(); }
        __syncthreads();
        const uint2* bA = sA[kc & 1];
        const uint2* bB = sB[kc & 1];

        #pragma unroll
        for (int kt = 0; kt < 2; ++kt) {
            int pb = kt * 8;
            uint2 Bf[4][2];
            #pragma unroll
            for (int fn = 0; fn < 4; ++fn) {
                int nb = wn * 32 + fn * 8 + qr;
                int swz = (nb & 3) << 2;
                Bf[fn][0] = bB[nb * 16 + ((pb + lq) ^ swz)];
                Bf[fn][1] = bB[nb * 16 + ((pb + 4 + lq) ^ swz)];
            }
            #pragma unroll
            for (int f = 0; f < 2; ++f) {
                int ra = wm * 32 + f * 16 + qr;
                int swz = (ra & 3) << 2;
                int k0 = (pb + lq) ^ swz, k1 = (pb + 4 + lq) ^ swz;
                uint2 A0 = bA[ra * 16 + k0];
                uint2 A1 = bA[(ra + 8) * 16 + k0];
                uint2 A2 = bA[ra * 16 + k1];
                uint2 A3 = bA[(ra + 8) * 16 + k1];
                #pragma unroll
                for (int fn = 0; fn < 4; ++fn)
                    mma3h(D[f][fn], A0, A1, A2, A3, Bf[fn][0], Bf[fn][1]);
            }
        }
        __syncthreads();
    }

    #pragma unroll
    for (int f = 0; f < 2; ++f)
        #pragma unroll
        for (int i = 0; i < 2; ++i) {
            int m = m0 + wm * 32 + f * 16 + qr + 8 * i;
            #pragma unroll
            for (int fn = 0; fn < 4; ++fn) {
                int n = n0 + wn * 32 + fn * 8 + (lq << 1);
                float2 bv = *(const float2*)&bias[n];
                float2 o = make_float2(D[f][fn][2*i] + bv.x, D[f][fn][2*i+1] + bv.y);
                *(float2*)&C[(size_t)m * N3 + n] = o;
            }
        }
}

// ---------------------------------------------------------------------------
// Persistent GRU recurrence — 12 warps (384 thr), warp = (bg, gate).
// Block = (batch-half, 16 units): 48 W rows resident, 64 h rows staged.
// Each warp computes ONE gate for both unit-groups (2 mma3h per kt) ->
// 3 warps/SMSP for latency hiding. Gates combined via 12 KB D-scratch
// carved from the h staging buffer (idle at epilogue time).
// smem = 196,608 + 2 x 16,384 = 229,376 B, 1 block/SM.
// ---------------------------------------------------------------------------
#define SW_U2  (48 * KP)                 // 24576 uint2 = 196,608 B
#define SHC_U2 (64 * 32)                 // per h chunk: 2048 uint2 = 16,384 B
#define REC_SMEM ((SW_U2 + 2 * SHC_U2) * (int)sizeof(uint2))   // 229,376 B

__device__ __forceinline__ float sigf(float x) { return 1.0f / (1.0f + expf(-x)); }

__global__ __launch_bounds__(RTH) void gru_recurrence(
    const float* __restrict__ xg, const uint2* __restrict__ WhhS,
    const float* __restrict__ bhh, uint2* __restrict__ hS0,
    uint2* __restrict__ hS1, uint2* __restrict__ yS)
{
    extern __shared__ uint2 smv[];
    uint2* sW    = smv;                           // [48][512] swizzled
    uint2* sH[2] = { smv + SW_U2, smv + SW_U2 + SHC_U2 };   // [64][32]
    float* Dsm   = (float*)sH[0];                 // 3*64*16 = 3072 f (12 KB)

    const int tid  = threadIdx.x;
    const int lane = tid & 31;
    const int w    = tid >> 5;
    const int qr   = lane >> 2;
    const int lq   = lane & 3;
    const int wb   = w & 3;               // batch group (m16)
    const int wg   = w >> 2;              // gate (0:r 1:z 2:n)
    const int bb   = blockIdx.x & 1;      // batch half
    const int j0   = (blockIdx.x >> 1) * 16;
    const int b0   = bb * 64;

    // one-time: copy this block's 48 pre-split Whh rows into smem (swizzled)
    for (int idx = tid; idx < 48 * 256; idx += RTH) {
        int r = idx >> 8;                 // 0..47 = gate*16+u
        int g = idx & 255;                // granule (2 pairs)
        int gate = r >> 4, u = r & 15;
        const uint2* src = WhhS + (size_t)(gate * HH + j0 + u) * KP + g * 2;
        uint4 v = *(const uint4*)src;
        int ks = (g * 2) ^ ((r & 3) << 2);
        sW[r * KP + ks]     = make_uint2(v.x, v.y);
        sW[r * KP + ks + 1] = make_uint2(v.z, v.w);
    }
    // epilogue work items are t-invariant: preload biases for both items
    float pbr[2], pbz[2], pbn[2], pbr1[2], pbz1[2], pbn1[2];
    #pragma unroll
    for (int it = 0; it < 2; ++it) {
        int item = tid + it * RTH;
        if (item < 512) {
            int up = item & 7;
            int j = j0 + 2 * up;
            pbr[it]  = bhh[j];            pbr1[it] = bhh[j + 1];
            pbz[it]  = bhh[HH + j];       pbz1[it] = bhh[HH + j + 1];
            pbn[it]  = bhh[2*HH + j];     pbn1[it] = bhh[2*HH + j + 1];
        }
    }
    __syncthreads();

    const uint2* hin  = hS0;
    uint2*       hout = hS1;

    for (int t = 0; t < TT; ++t) {
        float Dg[8] = {};                 // [ug][4] accumulators for gate wg

        auto stageH = [&](int c, int s) {
            uint2* buf = sH[s];
            for (int gi = tid; gi < 1024; gi += RTH) {     // 64 rows x 16 gran
                int row = gi >> 4, g = gi & 15;
                const uint2* src = hin + (size_t)(b0 + row) * KP + c * 32 + g * 2;
                int ks = (g * 2) ^ ((row & 3) << 2);
                cpa16(sptr(buf + row * 32 + ks), src);
            }
            CP_COMMIT();
        };

        stageH(0, 0);
        for (int c = 0; c < NCH; ++c) {
            if (c < NCH - 1) { stageH(c + 1, (c + 1) & 1); CP_WAIT1(); }
            else             { CP_WAIT0(); }
            __syncthreads();
            const uint2* bH = sH[c & 1];

            #pragma unroll
            for (int kt = 0; kt < 4; ++kt) {
                int pb = kt * 8;
                int ra = 16 * wb + qr;
                int swzA = (ra & 3) << 2;
                int k0 = (pb + lq) ^ swzA, k1 = (pb + 4 + lq) ^ swzA;
                uint2 A0 = bH[ra * 32 + k0];
                uint2 A1 = bH[(ra + 8) * 32 + k0];
                uint2 A2 = bH[ra * 32 + k1];
                uint2 A3 = bH[(ra + 8) * 32 + k1];

                int pW = c * 32 + pb;
                #pragma unroll
                for (int ug = 0; ug < 2; ++ug) {
                    int r = wg * 16 + ug * 8 + qr, swz = (r & 3) << 2;
                    mma3h(Dg + ug * 4, A0, A1, A2, A3,
                          sW[r * KP + ((pW + lq) ^ swz)],
                          sW[r * KP + ((pW + 4 + lq) ^ swz)]);
                }
            }
            __syncthreads();
        }

        // ---- epilogue: publish D fragments to smem scratch (sH[0] area) ----
        // last chunk read sH[1]; sH[0] free. Dsm[gate][b_local][unit]
        #pragma unroll
        for (int ug = 0; ug < 2; ++ug)
            #pragma unroll
            for (int i = 0; i < 2; ++i) {
                int bl = 16 * wb + qr + 8 * i;
                *(float2*)&Dsm[wg * 1024 + bl * 16 + ug * 8 + 2 * lq] =
                    make_float2(Dg[ug * 4 + 2 * i], Dg[ug * 4 + 2 * i + 1]);
            }
        __syncthreads();

        // ---- gates: item = (b_local, unit-pair), 512 items over 384 thr ----
        #pragma unroll
        for (int it = 0; it < 2; ++it) {
            int item = tid + it * RTH;
            if (item < 512) {
                int bl = item >> 3;
                int up = item & 7;
                int b  = b0 + bl;
                int j  = j0 + 2 * up;
                float2 dr = *(const float2*)&Dsm[0 * 1024 + bl * 16 + 2 * up];
                float2 dz = *(const float2*)&Dsm[1 * 1024 + bl * 16 + 2 * up];
                float2 dn = *(const float2*)&Dsm[2 * 1024 + bl * 16 + 2 * up];

                const size_t xo = ((size_t)b * TT + t) * N3 + j;
                float2 xr = *(const float2*)&xg[xo];
                float2 xz = *(const float2*)&xg[xo + HH];
                float2 xn = *(const float2*)&xg[xo + 2 * HH];
                const int pidx = (j0 >> 1) + up;
                uint2 hs = hin[(size_t)b * KP + pidx];
                float hp0 = lo_f(hs.x) + lo_f(hs.y);
                float hp1 = hi_f(hs.x) + hi_f(hs.y);

                float r0 = sigf(xr.x + dr.x + pbr[it]);
                float r1 = sigf(xr.y + dr.y + pbr1[it]);
                float z0 = sigf(xz.x + dz.x + pbz[it]);
                float z1 = sigf(xz.y + dz.y + pbz1[it]);
                float n0 = tanhf(xn.x + r0 * (dn.x + pbn[it]));
                float n1 = tanhf(xn.y + r1 * (dn.y + pbn1[it]));
                float h0 = (1.0f - z0) * n0 + z0 * hp0;
                float h1 = (1.0f - z1) * n1 + z1 * hp1;
                uint2 pk = splitpair(h0, h1);
                hout[(size_t)b * KP + pidx] = pk;
                if (yS) yS[((size_t)b * TT + t) * KP + pidx] = pk;
            }
        }

        grid_sync(NBLK);
        const uint2* tmp = hin; hin = hout; hout = (uint2*)tmp;
    }
    // TT even -> final hidden ends in hS0 (the initial buffer)
}

// ---------------------------------------------------------------------------
// predictions[b] = dot(h[b,:], lin_W) + lin_b
// ---------------------------------------------------------------------------
__global__ __launch_bounds__(256) void final_pred(
    const uint2* __restrict__ hS, const float* __restrict__ W,
    const float* __restrict__ bias, float* __restrict__ out)
{
    int b = blockIdx.x;
    float s = 0.f;
    for (int p = threadIdx.x; p < KP; p += 256) {
        uint2 u = hS[(size_t)b * KP + p];
        s += (lo_f(u.x) + lo_f(u.y)) * W[2 * p]
           + (hi_f(u.x) + hi_f(u.y)) * W[2 * p + 1];
    }
    #pragma unroll
    for (int o = 16; o; o >>= 1) s += __shfl_xor_sync(0xFFFFFFFFu, s, o);
    __shared__ float ws[8];
    if ((threadIdx.x & 31) == 0) ws[threadIdx.x >> 5] = s;
    __syncthreads();
    if (threadIdx.x == 0) {
        float t = 0.f;
        #pragma unroll
        for (int k = 0; k < 8; ++k) t += ws[k];
        out[b] = t + bias[0];
    }
}

// ---------------------------------------------------------------------------
// Launch — [0] prep_misc [1] prep_weights [2] gemm [3] recur [4] gemm
// [5] recur <- ncu (-s 5 -c 1) profiles the recurrence
// ---------------------------------------------------------------------------
extern "C" void kernel_launch(void* const* d_in, const int* in_sizes, int n_in,
                              void* d_out, int out_size)
{
    const float* rand_input = (const float*)d_in[1];
    const float* h0   = (const float*)d_in[2];
    const float* Wih0 = (const float*)d_in[7];
    const float* Whh0 = (const float*)d_in[8];
    const float* bih0 = (const float*)d_in[9];
    const float* bhh0 = (const float*)d_in[10];
    const float* Wih1 = (const float*)d_in[11];
    const float* Whh1 = (const float*)d_in[12];
    const float* bih1 = (const float*)d_in[13];
    const float* bhh1 = (const float*)d_in[14];
    const float* linW = (const float*)d_in[15];
    const float* linb = (const float*)d_in[16];
    float* out = (float*)d_out;

    float *xg;
    uint2 *inS, *yAS, *yBS, *WihS, *WhhS, *hA, *hB, *hC;
    cudaGetSymbolAddress((void**)&xg,   g_xg);
    cudaGetSymbolAddress((void**)&inS,  g_inS);
    cudaGetSymbolAddress((void**)&yAS,  g_yAS);
    cudaGetSymbolAddress((void**)&yBS,  g_yBS);
    cudaGetSymbolAddress((void**)&WihS, g_WihS);
    cudaGetSymbolAddress((void**)&WhhS, g_WhhS);
    cudaGetSymbolAddress((void**)&hA,   g_hA);
    cudaGetSymbolAddress((void**)&hB,   g_hB);
    cudaGetSymbolAddress((void**)&hC,   g_hC);
    uint2* WihS1 = WihS + (size_t)N3 * KP;
    uint2* WhhS1 = WhhS + (size_t)N3 * KP;

    cudaFuncSetAttribute(gru_recurrence,
                         cudaFuncAttributeMaxDynamicSharedMemorySize, REC_SMEM);
    cudaFuncSetAttribute(gemm_xg,
                         cudaFuncAttributeMaxDynamicSharedMemorySize, XG_SMEM);

    dim3 blk(256);
    dim3 blkR(RTH);
    dim3 grid_xg(N3 / 64, MFULL / 128);       // 48 x 384

    // [0] prep: rand_input + both h0 layers
    prep_misc<<<(INPAIRS + 2 * HPAIRS + 255) / 256, blk>>>(
        (const float2*)rand_input, (const float2*)h0, inS, hA, hB);
    // [1] prep: all 4 weight matrices
    prep_weights<<<(4 * WPAIRS + 255) / 256, blk>>>(
        (const float2*)Wih0, (const float2*)Whh0,
        (const float2*)Wih1, (const float2*)Whh1,
        WihS, WhhS, WihS1, WhhS1);

    auto run_pass = [&](const uint2* x, const uint2* WihSp, const float* bih,
                        const uint2* WhhSp, const float* bhh,
                        uint2* h_init, uint2* y) {
        gemm_xg<<<grid_xg, blk, XG_SMEM>>>(x, WihSp, bih, xg);
        gru_recurrence<<<NBLK, blkR, REC_SMEM>>>(xg, WhhSp, bhh, h_init, hC, y);
    };

    // [2,3] pass 1: layer0 on rand_input, h = h0[0] (hA)
    run_pass(inS, WihS, bih0, WhhS, bhh0, hA, yAS);
    // [4,5] pass 2: layer1 on yA, h = h0[1] (hB)   <- recurrence profiled
    run_pass(yAS, WihS1, bih1, WhhS1, bhh1, hB, yBS);

    // pass 3: layer0 on yB, h = 0
    cudaMemsetAsync(hA, 0, (size_t)HPAIRS * sizeof(uint2));
    run_pass(yBS, WihS, bih0, WhhS, bhh0, hA, yAS);

    // pass 4: layer1 on yA, h = 0 (y not needed)
    cudaMemsetAsync(hB, 0, (size_t)HPAIRS * sizeof(uint2));
    run_pass(yAS, WihS1, bih1, WhhS1, bhh1, hB, nullptr);

    final_pred<<<BB, blk>>>(hB, linW, linb, out);
}